// round 12
// baseline (speedup 1.0000x reference)
#include <cuda_runtime.h>
#include <cuda_bf16.h>
#include <cstdint>

#ifndef THR
#define THR 0.3f
#endif

// Floor-probe variant: 256 threads / 1024 rows / 12 KB tile per CTA.
// Doubles resident CTAs per SM (~8) and halves the per-CTA TMA-store drain,
// shrinking the exposed tail of the last wave.
//   loads  : warp-contiguous LDG.128 (4 full 128B lines per warp wavefront)
//   stores : one 12 KB cp.async.bulk per CTA, evict_first L2 policy
__global__ void __launch_bounds__(256) weighting_router_1k(
    const float4* __restrict__ xin,   // N/2 float4 (each float4 = 2 rows)
    float* __restrict__ out)          // 3N floats
{
    __shared__ __align__(128) float so[3072];   // 1024 rows * 3 = 12 KB

    const int tid = threadIdx.x;
    const long long blk = blockIdx.x;

    // ---- coalesced loads: warp spans 512B contiguous per LDG.128 ----
    const float4* src = xin + blk * 512;        // 512 float4 = 1024 rows
    float4 a = src[tid];                        // rows 2*tid,     2*tid+1
    float4 b = src[tid + 256];                  // rows 2*tid+512, 2*tid+513

    const float inv_hi = 1.0f / (1.0f - THR);   // 1/0.7
    const float inv_lo = 1.0f / THR;            // 1/0.3

    float h[4] = {a.x, a.z, b.x, b.z};
    float o[12];

#pragma unroll
    for (int i = 0; i < 4; i++) {
        float hv = h[i];
        bool hi = (hv >= THR);
        o[3 * i + 0] = hi ? (hv - THR) * inv_hi : 0.0f;
        o[3 * i + 1] = hi ? 0.0f : (THR - hv) * inv_lo;
        o[3 * i + 2] = hi ? (1.0f - hv) * inv_hi : hv * inv_lo;
    }

    // rows 2*tid,2*tid+1     -> f2 idx 3*tid
    // rows 2*tid+512,+513    -> f2 idx 3*tid + 768
    float2* so2 = (float2*)so;
#pragma unroll
    for (int j = 0; j < 3; j++)
        so2[3 * tid + j]       = make_float2(o[2 * j],     o[2 * j + 1]);
#pragma unroll
    for (int j = 0; j < 3; j++)
        so2[3 * tid + 768 + j] = make_float2(o[6 + 2 * j], o[6 + 2 * j + 1]);

    __syncthreads();

    // ---- single bulk TMA store with evict-first L2 policy ----
    if (tid == 0) {
        float* dst = out + blk * 3072;
        uint32_t so_addr = (uint32_t)__cvta_generic_to_shared(so);
        uint64_t pol_st;
        asm volatile("createpolicy.fractional.L2::evict_first.b64 %0, 1.0;"
                     : "=l"(pol_st));
        asm volatile("fence.proxy.async.shared::cta;" ::: "memory");
        asm volatile(
            "cp.async.bulk.global.shared::cta.bulk_group.L2::cache_hint "
            "[%0], [%1], %2, %3;"
            :: "l"(dst), "r"(so_addr), "r"(12288u), "l"(pol_st) : "memory");
        asm volatile("cp.async.bulk.commit_group;" ::: "memory");
        asm volatile("cp.async.bulk.wait_group 0;" ::: "memory");
    }
}

// Tail handler for rows not covered by the block-tiled kernel (n % 1024 != 0).
__global__ void weighting_router_tail(
    const float* __restrict__ x,
    float* __restrict__ out,
    int start_row, int n_rows)
{
    int i = start_row + blockIdx.x * blockDim.x + threadIdx.x;
    if (i >= n_rows) return;

    const float inv_hi = 1.0f / (1.0f - THR);
    const float inv_lo = 1.0f / THR;

    float hv = x[2 * i];
    bool hi = (hv >= THR);
    out[3 * i + 0] = hi ? (hv - THR) * inv_hi : 0.0f;
    out[3 * i + 1] = hi ? 0.0f : (THR - hv) * inv_lo;
    out[3 * i + 2] = hi ? (1.0f - hv) * inv_hi : hv * inv_lo;
}

extern "C" void kernel_launch(void* const* d_in, const int* in_sizes, int n_in,
                              void* d_out, int out_size)
{
    const float* x = (const float*)d_in[0];
    float* out = (float*)d_out;

    int n_rows = in_sizes[0] / 2;     // x is (N, 2)
    int n_blocks = n_rows / 1024;

    if (n_blocks > 0) {
        weighting_router_1k<<<n_blocks, 256>>>(
            (const float4*)x, out);
    }

    int done = n_blocks * 1024;
    int rem = n_rows - done;
    if (rem > 0) {
        int threads = 128;
        int blocks = (rem + threads - 1) / threads;
        weighting_router_tail<<<blocks, threads>>>(x, out, done, n_rows);
    }
}